// round 12
// baseline (speedup 1.0000x reference)
#include <cuda_runtime.h>

// Stage-1 partial batch sums of x: [z=16][i*1152+c]  (590 KB)
__device__ float g_part[16 * 9216];

// A: g_part[z][e] = sum of batches z*16..z*16+15.  x viewed as [256,2304] float4.
__global__ void __launch_bounds__(256) reduce_x1_kernel(const float* __restrict__ x) {
    const int col = blockIdx.x * 256 + threadIdx.x;   // 0..2303
    const int z = blockIdx.y;                         // 0..15
    const float4* p = reinterpret_cast<const float4*>(x) + (size_t)(z * 16) * 2304 + col;

    float4 a0 = __ldg(p);
    float4 a1 = __ldg(p + 2304);
    float4 a2 = __ldg(p + 2 * 2304);
    float4 a3 = __ldg(p + 3 * 2304);
    #pragma unroll
    for (int r = 1; r < 4; ++r) {
        const float4 v0 = __ldg(p + (size_t)(r * 4) * 2304);
        const float4 v1 = __ldg(p + (size_t)(r * 4 + 1) * 2304);
        const float4 v2 = __ldg(p + (size_t)(r * 4 + 2) * 2304);
        const float4 v3 = __ldg(p + (size_t)(r * 4 + 3) * 2304);
        a0.x += v0.x; a0.y += v0.y; a0.z += v0.z; a0.w += v0.w;
        a1.x += v1.x; a1.y += v1.y; a1.z += v1.z; a1.w += v1.w;
        a2.x += v2.x; a2.y += v2.y; a2.z += v2.z; a2.w += v2.w;
        a3.x += v3.x; a3.y += v3.y; a3.z += v3.z; a3.w += v3.w;
    }
    float4 a;
    a.x = (a0.x + a1.x) + (a2.x + a3.x);
    a.y = (a0.y + a1.y) + (a2.y + a3.y);
    a.z = (a0.z + a1.z) + (a2.z + a3.z);
    a.w = (a0.w + a1.w) + (a2.w + a3.w);
    reinterpret_cast<float4*>(g_part)[(size_t)z * 2304 + col] = a;

#if __CUDA_ARCH__ >= 900
    cudaTriggerProgrammaticLaunchCompletion();   // release dependents ASAP
#endif
}

// B: fully fused, PDL secondary. Issues its W loads BEFORE the grid
// dependency sync so the W stream overlaps reduce_x1's x stream.
__global__ void __launch_bounds__(320) fused_kernel(const float* __restrict__ W,
                                                    float* __restrict__ out) {
    const int t = threadIdx.x;            // 0..319
    const int c0 = blockIdx.x * 2;        // 576 blocks -> capsules c0, c0+1

    __shared__ float sm_part[256];        // [chunk*16 + v]
    __shared__ float sm_xs[16];           // [lc*8 + i]
    __shared__ float sm_usq[20];
    __shared__ float sm_b[20];
    __shared__ float sm_e[20];
    __shared__ float sm_k[20];

    const int lc = (t >= 160) ? 1 : 0;
    const int r = t - lc * 160;           // u*16 + s
    const int u = r >> 4;

    // W stream into flight first (independent of reduce_x1's output).
    const size_t e = (size_t)blockIdx.x * 320 + t;
    const float4* wp = reinterpret_cast<const float4*>(W) + e * 2;
    const float4 w0 = __ldg(wp);
    const float4 w1 = __ldg(wp + 1);

#if __CUDA_ARCH__ >= 900
    cudaGridDependencySynchronize();      // wait for reduce_x1 before g_part
#endif

    // xs partials: one load per thread; adjacent threads -> adjacent capsules.
    if (t < 256) {
        const int v = t & 15;
        const int cc = c0 + (v >> 3);
        const int i = v & 7;
        sm_part[t] = g_part[(size_t)(t >> 4) * 9216 + i * 1152 + cc];
    }
    __syncthreads();
    if (t < 16) {
        float a = 0.f;
        #pragma unroll
        for (int ch = 0; ch < 16; ++ch) a += sm_part[ch * 16 + t];
        sm_xs[t] = a;
    }
    __syncthreads();

    // us for this element
    const float* xp = sm_xs + lc * 8;
    const float us = w0.x * xp[0] + w0.y * xp[1] + w0.z * xp[2] + w0.w * xp[3]
                   + w1.x * xp[4] + w1.y * xp[5] + w1.z * xp[6] + w1.w * xp[7];

    // ||u_sum||^2 over the 16 s-lanes of this (c,u) group
    float q = us * us;
    q += __shfl_xor_sync(0xffffffffu, q, 1);
    q += __shfl_xor_sync(0xffffffffu, q, 2);
    q += __shfl_xor_sync(0xffffffffu, q, 4);
    q += __shfl_xor_sync(0xffffffffu, q, 8);
    if ((t & 15) == 0) sm_usq[lc * 10 + u] = q;
    __syncthreads();

    // Scalar routing on threads 0..19 (t = cc*10 + uu), inside warp 0.
    if (t < 20) {
        const int cc = (t >= 10) ? 1 : 0;
        const float usq = sm_usq[t];
        float b = 0.f;
        float cij = 0.1f;                 // softmax of zero logits, exact
        float k = 0.f;

        #pragma unroll
        for (int it = 0; it < 3; ++it) {
            const float msq = cij * cij * usq;
            const float coef = msq / (1.0f + msq) * rsqrtf(msq);
            k = coef * cij;

            if (it < 2) {
                b += k * usq * (1.0f / 256.0f);
                sm_b[t] = b;
                __syncwarp(0x000FFFFFu);
                const float* bb = sm_b + cc * 10;
                float m = bb[0];
                #pragma unroll
                for (int j = 1; j < 10; ++j) m = fmaxf(m, bb[j]);
                const float ex = __expf(b - m);
                sm_e[t] = ex;
                __syncwarp(0x000FFFFFu);
                const float* ep = sm_e + cc * 10;
                float d = ep[0];
                #pragma unroll
                for (int j = 1; j < 10; ++j) d += ep[j];
                cij = ex / d;
            }
        }
        sm_k[t] = k;
    }
    __syncthreads();

    out[e] = sm_k[lc * 10 + u] * us;
}

extern "C" void kernel_launch(void* const* d_in, const int* in_sizes, int n_in,
                              void* d_out, int out_size) {
    const float* x = (const float*)d_in[0];   // [256, 8, 1152]
    const float* W = (const float*)d_in[1];   // [1, 1152, 10, 16, 8]
    float* out = (float*)d_out;               // [1152, 10, 16]

    reduce_x1_kernel<<<dim3(9, 16), 256>>>(x);

    // Secondary launch with programmatic dependent launch: starts while
    // reduce_x1 runs; fused_kernel gates on cudaGridDependencySynchronize().
    cudaLaunchConfig_t cfg = {};
    cfg.gridDim = dim3(576);
    cfg.blockDim = dim3(320);
    cfg.dynamicSmemBytes = 0;
    cfg.stream = 0;
    cudaLaunchAttribute attr[1];
    attr[0].id = cudaLaunchAttributeProgrammaticStreamSerialization;
    attr[0].val.programmaticStreamSerializationAllowed = 1;
    cfg.attrs = attr;
    cfg.numAttrs = 1;
    cudaLaunchKernelEx(&cfg, fused_kernel, W, out);
}